// round 13
// baseline (speedup 1.0000x reference)
#include <cuda_runtime.h>

#define NDIMS  3
#define NCOLS  500000
#define RANKV  64
#define K1V    32
#define BATCHV 8192
#define BPB    8                          /* batch elements per block */
#define NBLK   (BATCHV / BPB)             /* 1024 blocks */
#define NGATH  (NDIMS * BATCHV * RANKV)

__device__ float2       g_part[NBLK];
__device__ unsigned int g_ticket = 0;

// ---------------------------------------------------------------------------
// Fast natural log (Cephes logf polynomial, FMA-pipe only). x > 0 (normal).
// ---------------------------------------------------------------------------
__device__ __forceinline__ float fast_ln(float x) {
    int   i = __float_as_int(x);
    int   e = (i - 0x3F3504F3) >> 23;
    float m = __int_as_float(i - (e << 23));
    float z = m - 1.0f;
    float p =            7.0376836292e-2f;
    p = fmaf(p, z, -1.1514610310e-1f);
    p = fmaf(p, z,  1.1676998740e-1f);
    p = fmaf(p, z, -1.2420140846e-1f);
    p = fmaf(p, z,  1.4249322787e-1f);
    p = fmaf(p, z, -1.6668057665e-1f);
    p = fmaf(p, z,  2.0000714765e-1f);
    p = fmaf(p, z, -2.4999993993e-1f);
    p = fmaf(p, z,  3.3333331174e-1f);
    float z2 = z * z;
    float y  = p * z2 * z;
    y = fmaf(-0.5f, z2, y);
    return fmaf((float)e, 0.693147180559945f, z + y);
}

__device__ __forceinline__ void pfL2(const void* p) {
    asm volatile("prefetch.global.L2 [%0];" :: "l"(p));
}

// ---------------------------------------------------------------------------
// R12 winner + deeper prefetch pipeline:
//  - prologue prefetches elements 0 and 1 (cold-start coverage)
//  - loop iteration i prefetches element i+2 (two compute windows of slack,
//    enough to cover the full DRAM->L2 fill before the LDGs arrive)
// Layout unchanged: 1024 blocks x 256 thr, half-warp (16 lanes x float4) per
// MC sample, 2 samples per warp per element, KL on warp 0.
// ---------------------------------------------------------------------------
__global__ __launch_bounds__(256, 4)
void fused_k(const int*   __restrict__ entries,
             const float* __restrict__ ys,
             const float* __restrict__ means,
             const float* __restrict__ chols,
             const float* __restrict__ eps,
             float*       __restrict__ out) {
    const int t    = threadIdx.x;
    const int w    = t >> 5;
    const int lane = t & 31;
    const int h    = lane >> 4;      // half: which k of the pair
    const int r16  = lane & 15;      // rank/4 slice index

    __shared__ int   s_ent[BPB * 3];
    __shared__ float s_y[BPB];

    const int b0 = blockIdx.x * BPB;
    if (t < BPB * 3) s_ent[t] = __ldg(entries + b0 * 3 + t);
    if (t < BPB)     s_y[t]   = __ldg(ys + b0 + t);

    const float4* M4 = (const float4*)means;
    const float4* C4 = (const float4*)chols;
    const float4* E4 = (const float4*)eps;
    const int dstride = BATCHV * K1V * 16;            // per-dim stride (float4)
    const int k0 = 2 * w + h;
    const int k1 = k0 + 16;

    // ---- prologue: warm L2 for elements 0 and 1 (eps only; gather rows for
    // 0/1 are prefetched after s_ent is visible, below) ----
    if ((r16 & 7) == 0) {
        #pragma unroll
        for (int pe = 0; pe < 2; pe++) {
            const int nbase = (b0 + pe) * K1V * 16 + r16;
            pfL2(E4 + nbase + k0 * 16);
            pfL2(E4 + nbase + k0 * 16 + dstride);
            pfL2(E4 + nbase + k0 * 16 + 2 * dstride);
            pfL2(E4 + nbase + k1 * 16);
            pfL2(E4 + nbase + k1 * 16 + dstride);
            pfL2(E4 + nbase + k1 * 16 + 2 * dstride);
        }
    }
    __syncthreads();

    float lp_acc = 0.f;
    float kl_acc = 0.f;

    #pragma unroll 2
    for (int i = 0; i < BPB; i++) {
        const int b = b0 + i;

        // ---- prefetch element i+2 into L2 (zero registers, no sync) ----
        if (i + 2 < BPB && (r16 & 7) == 0) {
            const int nbase = (b + 2) * K1V * 16 + r16;
            pfL2(E4 + nbase + k0 * 16);
            pfL2(E4 + nbase + k0 * 16 + dstride);
            pfL2(E4 + nbase + k0 * 16 + 2 * dstride);
            pfL2(E4 + nbase + k1 * 16);
            pfL2(E4 + nbase + k1 * 16 + dstride);
            pfL2(E4 + nbase + k1 * 16 + 2 * dstride);
        }
        // gather rows for i+1 (shared across warps; warp 0 covers them)
        if (i + 1 < BPB && w == 0 && (r16 & 7) == 0) {
            const int q0 = s_ent[(i + 1) * 3 + 0];
            const int q1 = s_ent[(i + 1) * 3 + 1];
            const int q2 = s_ent[(i + 1) * 3 + 2];
            pfL2(M4 + (0 * NCOLS + q0) * 16 + r16);
            pfL2(M4 + (1 * NCOLS + q1) * 16 + r16);
            pfL2(M4 + (2 * NCOLS + q2) * 16 + r16);
            pfL2(C4 + (0 * NCOLS + q0) * 16 + r16);
            pfL2(C4 + (1 * NCOLS + q1) * 16 + r16);
            pfL2(C4 + (2 * NCOLS + q2) * 16 + r16);
        }

        // ---- loads for element i ----
        const int r0 = s_ent[i * 3 + 0];
        const int r1 = s_ent[i * 3 + 1];
        const int r2 = s_ent[i * 3 + 2];
        const int gi0 = (0 * NCOLS + r0) * 16 + r16;
        const int gi1 = (1 * NCOLS + r1) * 16 + r16;
        const int gi2 = (2 * NCOLS + r2) * 16 + r16;

        const int base = b * K1V * 16 + r16;
        const float4 eA0 = __ldcs(E4 + base + k0 * 16);
        const float4 eB0 = __ldcs(E4 + base + k0 * 16 + dstride);
        const float4 eC0 = __ldcs(E4 + base + k0 * 16 + 2 * dstride);
        const float4 eA1 = __ldcs(E4 + base + k1 * 16);
        const float4 eB1 = __ldcs(E4 + base + k1 * 16 + dstride);
        const float4 eC1 = __ldcs(E4 + base + k1 * 16 + 2 * dstride);

        const float4 m0 = __ldg(M4 + gi0), m1 = __ldg(M4 + gi1), m2 = __ldg(M4 + gi2);
        const float y = s_y[i];

        // S = L^2; 'c' values die immediately after these squares.
        float4 l0, l1, l2;
        {
            const float4 c0 = __ldg(C4 + gi0), c1 = __ldg(C4 + gi1), c2 = __ldg(C4 + gi2);
            l0.x = c0.x*c0.x; l0.y = c0.y*c0.y; l0.z = c0.z*c0.z; l0.w = c0.w*c0.w;
            l1.x = c1.x*c1.x; l1.y = c1.y*c1.y; l1.z = c1.z*c1.z; l1.w = c1.w*c1.w;
            l2.x = c2.x*c2.x; l2.y = c2.y*c2.y; l2.z = c2.z*c2.z; l2.w = c2.w*c2.w;
        }

        float s0, s1;
        {
            float ax = fmaf(eA0.x, l0.x, m0.x) * fmaf(eB0.x, l1.x, m1.x) * fmaf(eC0.x, l2.x, m2.x);
            float ay = fmaf(eA0.y, l0.y, m0.y) * fmaf(eB0.y, l1.y, m1.y) * fmaf(eC0.y, l2.y, m2.y);
            float az = fmaf(eA0.z, l0.z, m0.z) * fmaf(eB0.z, l1.z, m1.z) * fmaf(eC0.z, l2.z, m2.z);
            float aw = fmaf(eA0.w, l0.w, m0.w) * fmaf(eB0.w, l1.w, m1.w) * fmaf(eC0.w, l2.w, m2.w);
            s0 = (ax + ay) + (az + aw);
        }
        {
            float ax = fmaf(eA1.x, l0.x, m0.x) * fmaf(eB1.x, l1.x, m1.x) * fmaf(eC1.x, l2.x, m2.x);
            float ay = fmaf(eA1.y, l0.y, m0.y) * fmaf(eB1.y, l1.y, m1.y) * fmaf(eC1.y, l2.y, m2.y);
            float az = fmaf(eA1.z, l0.z, m0.z) * fmaf(eB1.z, l1.z, m1.z) * fmaf(eC1.z, l2.z, m2.z);
            float aw = fmaf(eA1.w, l0.w, m0.w) * fmaf(eB1.w, l1.w, m1.w) * fmaf(eC1.w, l2.w, m2.w);
            s1 = (ax + ay) + (az + aw);
        }
        // Reduce over rank within each 16-lane group; both chains run with ILP.
        #pragma unroll
        for (int o = 1; o < 16; o <<= 1) {
            s0 += __shfl_xor_sync(0xffffffffu, s0, o);
            s1 += __shfl_xor_sync(0xffffffffu, s1, o);
        }
        if (r16 == 0) {
            float d0 = s0 - y, d1 = s1 - y;
            lp_acc = fmaf(-0.5f * d0, d0, fmaf(-0.5f * d1, d1, lp_acc));
        }

        // KL on warp 0 only; both 16-lane halves duplicate -> 0.5x at the end.
        // kl = 0.5*(l^2 + m^2 - 1) - ln(l),  l = c^2  (log(S^2) = 2*ln(c^2))
        if (w == 0) {
            float klp;
            klp = 0.5f * ( fmaf(l0.x, l0.x, m0.x*m0.x) + fmaf(l0.y, l0.y, m0.y*m0.y)
                         + fmaf(l0.z, l0.z, m0.z*m0.z) + fmaf(l0.w, l0.w, m0.w*m0.w)
                         + fmaf(l1.x, l1.x, m1.x*m1.x) + fmaf(l1.y, l1.y, m1.y*m1.y)
                         + fmaf(l1.z, l1.z, m1.z*m1.z) + fmaf(l1.w, l1.w, m1.w*m1.w)
                         + fmaf(l2.x, l2.x, m2.x*m2.x) + fmaf(l2.y, l2.y, m2.y*m2.y)
                         + fmaf(l2.z, l2.z, m2.z*m2.z) + fmaf(l2.w, l2.w, m2.w*m2.w));
            klp -= ( fast_ln(l0.x) + fast_ln(l0.y) + fast_ln(l0.z) + fast_ln(l0.w)
                   + fast_ln(l1.x) + fast_ln(l1.y) + fast_ln(l1.z) + fast_ln(l1.w)
                   + fast_ln(l2.x) + fast_ln(l2.y) + fast_ln(l2.z) + fast_ln(l2.w) );
            kl_acc += klp;
        }
    }

    // ---- once-per-block reduction ----
    #pragma unroll
    for (int o = 16; o; o >>= 1) {
        lp_acc += __shfl_xor_sync(0xffffffffu, lp_acc, o);
        kl_acc += __shfl_xor_sync(0xffffffffu, kl_acc, o);
    }
    __shared__ float wlp[8];
    __shared__ float wkl;
    __shared__ bool  isLast;
    if (lane == 0) { wlp[w] = lp_acc; if (w == 0) wkl = 0.5f * kl_acc; }
    __syncthreads();

    if (t == 0) {
        float s = ((wlp[0] + wlp[1]) + (wlp[2] + wlp[3]))
                + ((wlp[4] + wlp[5]) + (wlp[6] + wlp[7]));
        g_part[blockIdx.x] = make_float2(s, wkl);
        __threadfence();
        unsigned int old = atomicAdd(&g_ticket, 1u);
        isLast = (old == (unsigned int)(gridDim.x - 1));
        if (isLast) g_ticket = 0;                    // reset for next replay
    }
    __syncthreads();

    // Last block: final reduction over all per-block partials.
    if (isLast) {
        double se = 0.0, sk = 0.0;
        for (int i = t; i < NBLK; i += 256) {
            float2 p = g_part[i];
            se += (double)p.x;
            sk += (double)p.y;
        }
        #pragma unroll
        for (int o = 16; o; o >>= 1) {
            se += __shfl_xor_sync(0xffffffffu, se, o);
            sk += __shfl_xor_sync(0xffffffffu, sk, o);
        }
        __shared__ double dse[8], dsk[8];
        if (lane == 0) { dse[w] = se; dsk[w] = sk; }
        __syncthreads();
        if (t == 0) {
            double E  = 0.0, KL = 0.0;
            #pragma unroll
            for (int i = 0; i < 8; i++) { E += dse[i]; KL += dsk[i]; }
            E = E / (double)K1V - (double)BATCHV * 0.91893853320467274;
            KL -= 0.5 * (double)NGATH;
            out[0] = (float)(-(100.0 * E - KL / (double)BATCHV));
        }
    }
}

extern "C" void kernel_launch(void* const* d_in, const int* in_sizes, int n_in,
                              void* d_out, int out_size) {
    const int*   entries = (const int*)  d_in[0];
    const float* ys      = (const float*)d_in[1];
    const float* means   = (const float*)d_in[2];
    const float* chols   = (const float*)d_in[3];
    const float* eps     = (const float*)d_in[4];

    fused_k<<<NBLK, 256>>>(entries, ys, means, chols, eps, (float*)d_out);
}

// round 14
// speedup vs baseline: 1.1718x; 1.1718x over previous
#include <cuda_runtime.h>

#define NDIMS  3
#define NCOLS  500000
#define RANKV  64
#define K1V    32
#define BATCHV 8192
#define BPB    16                         /* batch elements per block */
#define NBLK   (BATCHV / BPB)             /* 512 blocks -> single wave */
#define NGATH  (NDIMS * BATCHV * RANKV)

__device__ float2       g_part[NBLK];
__device__ unsigned int g_ticket = 0;

// ---------------------------------------------------------------------------
// Fast natural log (Cephes logf polynomial, FMA-pipe only). x > 0 (normal).
// ---------------------------------------------------------------------------
__device__ __forceinline__ float fast_ln(float x) {
    int   i = __float_as_int(x);
    int   e = (i - 0x3F3504F3) >> 23;
    float m = __int_as_float(i - (e << 23));
    float z = m - 1.0f;
    float p =            7.0376836292e-2f;
    p = fmaf(p, z, -1.1514610310e-1f);
    p = fmaf(p, z,  1.1676998740e-1f);
    p = fmaf(p, z, -1.2420140846e-1f);
    p = fmaf(p, z,  1.4249322787e-1f);
    p = fmaf(p, z, -1.6668057665e-1f);
    p = fmaf(p, z,  2.0000714765e-1f);
    p = fmaf(p, z, -2.4999993993e-1f);
    p = fmaf(p, z,  3.3333331174e-1f);
    float z2 = z * z;
    float y  = p * z2 * z;
    y = fmaf(-0.5f, z2, y);
    return fmaf((float)e, 0.693147180559945f, z + y);
}

__device__ __forceinline__ void pfL2(const void* p) {
    asm volatile("prefetch.global.L2 [%0];" :: "l"(p));
}

// ---------------------------------------------------------------------------
// Exact R12 winner structure (37.6us) with BPB 8 -> 16:
//  - same distance-1 L2 prefetch placement (top of iteration i covers i+1)
//  - longer loop amortizes the 1-2 cold iterations over 16 elements
//  - grid 512 = single resident wave at occ 4 (no wave-transition tail)
// Layout: half-warp (16 lanes x float4 = rank 64), 2 MC samples per warp per
// element, KL on warp 0 only.
// ---------------------------------------------------------------------------
__global__ __launch_bounds__(256, 4)
void fused_k(const int*   __restrict__ entries,
             const float* __restrict__ ys,
             const float* __restrict__ means,
             const float* __restrict__ chols,
             const float* __restrict__ eps,
             float*       __restrict__ out) {
    const int t    = threadIdx.x;
    const int w    = t >> 5;
    const int lane = t & 31;
    const int h    = lane >> 4;      // half: which k of the pair
    const int r16  = lane & 15;      // rank/4 slice index

    __shared__ int   s_ent[BPB * 3];
    __shared__ float s_y[BPB];

    const int b0 = blockIdx.x * BPB;
    if (t < BPB * 3) s_ent[t] = __ldg(entries + b0 * 3 + t);
    if (t < BPB)     s_y[t]   = __ldg(ys + b0 + t);
    __syncthreads();

    const float4* M4 = (const float4*)means;
    const float4* C4 = (const float4*)chols;
    const float4* E4 = (const float4*)eps;
    const int dstride = BATCHV * K1V * 16;            // per-dim stride (float4)
    const int k0 = 2 * w + h;
    const int k1 = k0 + 16;

    float lp_acc = 0.f;
    float kl_acc = 0.f;

    #pragma unroll 2
    for (int i = 0; i < BPB; i++) {
        const int b = b0 + i;

        // ---- prefetch element i+1 into L2 (zero registers, no sync) ----
        if (i + 1 < BPB && (r16 & 7) == 0) {
            const int nbase = (b + 1) * K1V * 16 + r16;
            pfL2(E4 + nbase + k0 * 16);
            pfL2(E4 + nbase + k0 * 16 + dstride);
            pfL2(E4 + nbase + k0 * 16 + 2 * dstride);
            pfL2(E4 + nbase + k1 * 16);
            pfL2(E4 + nbase + k1 * 16 + dstride);
            pfL2(E4 + nbase + k1 * 16 + 2 * dstride);
            if (w == 0) {   // gather rows for i+1 (shared by all warps)
                const int q0 = s_ent[(i + 1) * 3 + 0];
                const int q1 = s_ent[(i + 1) * 3 + 1];
                const int q2 = s_ent[(i + 1) * 3 + 2];
                pfL2(M4 + (0 * NCOLS + q0) * 16 + r16);
                pfL2(M4 + (1 * NCOLS + q1) * 16 + r16);
                pfL2(M4 + (2 * NCOLS + q2) * 16 + r16);
                pfL2(C4 + (0 * NCOLS + q0) * 16 + r16);
                pfL2(C4 + (1 * NCOLS + q1) * 16 + r16);
                pfL2(C4 + (2 * NCOLS + q2) * 16 + r16);
            }
        }

        // ---- loads for element i ----
        const int r0 = s_ent[i * 3 + 0];
        const int r1 = s_ent[i * 3 + 1];
        const int r2 = s_ent[i * 3 + 2];
        const int gi0 = (0 * NCOLS + r0) * 16 + r16;
        const int gi1 = (1 * NCOLS + r1) * 16 + r16;
        const int gi2 = (2 * NCOLS + r2) * 16 + r16;

        const int base = b * K1V * 16 + r16;
        const float4 eA0 = __ldcs(E4 + base + k0 * 16);
        const float4 eB0 = __ldcs(E4 + base + k0 * 16 + dstride);
        const float4 eC0 = __ldcs(E4 + base + k0 * 16 + 2 * dstride);
        const float4 eA1 = __ldcs(E4 + base + k1 * 16);
        const float4 eB1 = __ldcs(E4 + base + k1 * 16 + dstride);
        const float4 eC1 = __ldcs(E4 + base + k1 * 16 + 2 * dstride);

        const float4 m0 = __ldg(M4 + gi0), m1 = __ldg(M4 + gi1), m2 = __ldg(M4 + gi2);
        const float y = s_y[i];

        // S = L^2; 'c' values die immediately after these squares.
        float4 l0, l1, l2;
        {
            const float4 c0 = __ldg(C4 + gi0), c1 = __ldg(C4 + gi1), c2 = __ldg(C4 + gi2);
            l0.x = c0.x*c0.x; l0.y = c0.y*c0.y; l0.z = c0.z*c0.z; l0.w = c0.w*c0.w;
            l1.x = c1.x*c1.x; l1.y = c1.y*c1.y; l1.z = c1.z*c1.z; l1.w = c1.w*c1.w;
            l2.x = c2.x*c2.x; l2.y = c2.y*c2.y; l2.z = c2.z*c2.z; l2.w = c2.w*c2.w;
        }

        float s0, s1;
        {
            float ax = fmaf(eA0.x, l0.x, m0.x) * fmaf(eB0.x, l1.x, m1.x) * fmaf(eC0.x, l2.x, m2.x);
            float ay = fmaf(eA0.y, l0.y, m0.y) * fmaf(eB0.y, l1.y, m1.y) * fmaf(eC0.y, l2.y, m2.y);
            float az = fmaf(eA0.z, l0.z, m0.z) * fmaf(eB0.z, l1.z, m1.z) * fmaf(eC0.z, l2.z, m2.z);
            float aw = fmaf(eA0.w, l0.w, m0.w) * fmaf(eB0.w, l1.w, m1.w) * fmaf(eC0.w, l2.w, m2.w);
            s0 = (ax + ay) + (az + aw);
        }
        {
            float ax = fmaf(eA1.x, l0.x, m0.x) * fmaf(eB1.x, l1.x, m1.x) * fmaf(eC1.x, l2.x, m2.x);
            float ay = fmaf(eA1.y, l0.y, m0.y) * fmaf(eB1.y, l1.y, m1.y) * fmaf(eC1.y, l2.y, m2.y);
            float az = fmaf(eA1.z, l0.z, m0.z) * fmaf(eB1.z, l1.z, m1.z) * fmaf(eC1.z, l2.z, m2.z);
            float aw = fmaf(eA1.w, l0.w, m0.w) * fmaf(eB1.w, l1.w, m1.w) * fmaf(eC1.w, l2.w, m2.w);
            s1 = (ax + ay) + (az + aw);
        }
        // Reduce over rank within each 16-lane group; both chains run with ILP.
        #pragma unroll
        for (int o = 1; o < 16; o <<= 1) {
            s0 += __shfl_xor_sync(0xffffffffu, s0, o);
            s1 += __shfl_xor_sync(0xffffffffu, s1, o);
        }
        if (r16 == 0) {
            float d0 = s0 - y, d1 = s1 - y;
            lp_acc = fmaf(-0.5f * d0, d0, fmaf(-0.5f * d1, d1, lp_acc));
        }

        // KL on warp 0 only; both 16-lane halves duplicate -> 0.5x at the end.
        // kl = 0.5*(l^2 + m^2 - 1) - ln(l),  l = c^2  (log(S^2) = 2*ln(c^2))
        if (w == 0) {
            float klp;
            klp = 0.5f * ( fmaf(l0.x, l0.x, m0.x*m0.x) + fmaf(l0.y, l0.y, m0.y*m0.y)
                         + fmaf(l0.z, l0.z, m0.z*m0.z) + fmaf(l0.w, l0.w, m0.w*m0.w)
                         + fmaf(l1.x, l1.x, m1.x*m1.x) + fmaf(l1.y, l1.y, m1.y*m1.y)
                         + fmaf(l1.z, l1.z, m1.z*m1.z) + fmaf(l1.w, l1.w, m1.w*m1.w)
                         + fmaf(l2.x, l2.x, m2.x*m2.x) + fmaf(l2.y, l2.y, m2.y*m2.y)
                         + fmaf(l2.z, l2.z, m2.z*m2.z) + fmaf(l2.w, l2.w, m2.w*m2.w));
            klp -= ( fast_ln(l0.x) + fast_ln(l0.y) + fast_ln(l0.z) + fast_ln(l0.w)
                   + fast_ln(l1.x) + fast_ln(l1.y) + fast_ln(l1.z) + fast_ln(l1.w)
                   + fast_ln(l2.x) + fast_ln(l2.y) + fast_ln(l2.z) + fast_ln(l2.w) );
            kl_acc += klp;
        }
    }

    // ---- once-per-block reduction ----
    #pragma unroll
    for (int o = 16; o; o >>= 1) {
        lp_acc += __shfl_xor_sync(0xffffffffu, lp_acc, o);
        kl_acc += __shfl_xor_sync(0xffffffffu, kl_acc, o);
    }
    __shared__ float wlp[8];
    __shared__ float wkl;
    __shared__ bool  isLast;
    if (lane == 0) { wlp[w] = lp_acc; if (w == 0) wkl = 0.5f * kl_acc; }
    __syncthreads();

    if (t == 0) {
        float s = ((wlp[0] + wlp[1]) + (wlp[2] + wlp[3]))
                + ((wlp[4] + wlp[5]) + (wlp[6] + wlp[7]));
        g_part[blockIdx.x] = make_float2(s, wkl);
        __threadfence();
        unsigned int old = atomicAdd(&g_ticket, 1u);
        isLast = (old == (unsigned int)(gridDim.x - 1));
        if (isLast) g_ticket = 0;                    // reset for next replay
    }
    __syncthreads();

    // Last block: final reduction over all per-block partials.
    if (isLast) {
        double se = 0.0, sk = 0.0;
        for (int i = t; i < NBLK; i += 256) {
            float2 p = g_part[i];
            se += (double)p.x;
            sk += (double)p.y;
        }
        #pragma unroll
        for (int o = 16; o; o >>= 1) {
            se += __shfl_xor_sync(0xffffffffu, se, o);
            sk += __shfl_xor_sync(0xffffffffu, sk, o);
        }
        __shared__ double dse[8], dsk[8];
        if (lane == 0) { dse[w] = se; dsk[w] = sk; }
        __syncthreads();
        if (t == 0) {
            double E  = 0.0, KL = 0.0;
            #pragma unroll
            for (int i = 0; i < 8; i++) { E += dse[i]; KL += dsk[i]; }
            E = E / (double)K1V - (double)BATCHV * 0.91893853320467274;
            KL -= 0.5 * (double)NGATH;
            out[0] = (float)(-(100.0 * E - KL / (double)BATCHV));
        }
    }
}

extern "C" void kernel_launch(void* const* d_in, const int* in_sizes, int n_in,
                              void* d_out, int out_size) {
    const int*   entries = (const int*)  d_in[0];
    const float* ys      = (const float*)d_in[1];
    const float* means   = (const float*)d_in[2];
    const float* chols   = (const float*)d_in[3];
    const float* eps     = (const float*)d_in[4];

    fused_k<<<NBLK, 256>>>(entries, ys, means, chols, eps, (float*)d_out);
}

// round 15
// speedup vs baseline: 1.3255x; 1.1312x over previous
#include <cuda_runtime.h>

#define NDIMS  3
#define NCOLS  500000
#define RANKV  64
#define K1V    32
#define BATCHV 8192
#define BPB    16                         /* batch elements per block */
#define NBLK   (BATCHV / BPB)             /* 512 blocks -> single wave */
#define NGATH  (NDIMS * BATCHV * RANKV)

__device__ float2       g_part[NBLK];
__device__ unsigned int g_ticket = 0;

// ---------------------------------------------------------------------------
// Fast natural log (Cephes logf polynomial, FMA-pipe only). x > 0 (normal).
// ---------------------------------------------------------------------------
__device__ __forceinline__ float fast_ln(float x) {
    int   i = __float_as_int(x);
    int   e = (i - 0x3F3504F3) >> 23;
    float m = __int_as_float(i - (e << 23));
    float z = m - 1.0f;
    float p =            7.0376836292e-2f;
    p = fmaf(p, z, -1.1514610310e-1f);
    p = fmaf(p, z,  1.1676998740e-1f);
    p = fmaf(p, z, -1.2420140846e-1f);
    p = fmaf(p, z,  1.4249322787e-1f);
    p = fmaf(p, z, -1.6668057665e-1f);
    p = fmaf(p, z,  2.0000714765e-1f);
    p = fmaf(p, z, -2.4999993993e-1f);
    p = fmaf(p, z,  3.3333331174e-1f);
    float z2 = z * z;
    float y  = p * z2 * z;
    y = fmaf(-0.5f, z2, y);
    return fmaf((float)e, 0.693147180559945f, z + y);
}

__device__ __forceinline__ void pfL2(const void* p) {
    asm volatile("prefetch.global.L2 [%0];" :: "l"(p));
}

// ---------------------------------------------------------------------------
// R14 winner (35.6us) with two issue-order micro-fixes:
//  - eps prefetch for i+1 issues AFTER iteration i's critical eps LDGs
//    (prefetches are not latency-sensitive; the LDGs are)
//  - gather-row prefetch dropped (L1/L2-resident across the block's warps;
//    cost ~6 issue slots/iter for ~no latency benefit)
// Layout: half-warp (16 lanes x float4 = rank 64), 2 MC samples per warp per
// element, KL on warp 0 only; BPB=16, grid 512 (single resident wave).
// ---------------------------------------------------------------------------
__global__ __launch_bounds__(256, 4)
void fused_k(const int*   __restrict__ entries,
             const float* __restrict__ ys,
             const float* __restrict__ means,
             const float* __restrict__ chols,
             const float* __restrict__ eps,
             float*       __restrict__ out) {
    const int t    = threadIdx.x;
    const int w    = t >> 5;
    const int lane = t & 31;
    const int h    = lane >> 4;      // half: which k of the pair
    const int r16  = lane & 15;      // rank/4 slice index

    __shared__ int   s_ent[BPB * 3];
    __shared__ float s_y[BPB];

    const int b0 = blockIdx.x * BPB;
    if (t < BPB * 3) s_ent[t] = __ldg(entries + b0 * 3 + t);
    if (t < BPB)     s_y[t]   = __ldg(ys + b0 + t);
    __syncthreads();

    const float4* M4 = (const float4*)means;
    const float4* C4 = (const float4*)chols;
    const float4* E4 = (const float4*)eps;
    const int dstride = BATCHV * K1V * 16;            // per-dim stride (float4)
    const int k0 = 2 * w + h;
    const int k1 = k0 + 16;

    float lp_acc = 0.f;
    float kl_acc = 0.f;

    #pragma unroll 2
    for (int i = 0; i < BPB; i++) {
        const int b = b0 + i;

        // ---- critical loads for element i FIRST ----
        const int r0 = s_ent[i * 3 + 0];
        const int r1 = s_ent[i * 3 + 1];
        const int r2 = s_ent[i * 3 + 2];
        const int gi0 = (0 * NCOLS + r0) * 16 + r16;
        const int gi1 = (1 * NCOLS + r1) * 16 + r16;
        const int gi2 = (2 * NCOLS + r2) * 16 + r16;

        const int base = b * K1V * 16 + r16;
        const float4 eA0 = __ldcs(E4 + base + k0 * 16);
        const float4 eB0 = __ldcs(E4 + base + k0 * 16 + dstride);
        const float4 eC0 = __ldcs(E4 + base + k0 * 16 + 2 * dstride);
        const float4 eA1 = __ldcs(E4 + base + k1 * 16);
        const float4 eB1 = __ldcs(E4 + base + k1 * 16 + dstride);
        const float4 eC1 = __ldcs(E4 + base + k1 * 16 + 2 * dstride);

        const float4 m0 = __ldg(M4 + gi0), m1 = __ldg(M4 + gi1), m2 = __ldg(M4 + gi2);
        const float y = s_y[i];

        // S = L^2; 'c' values die immediately after these squares.
        float4 l0, l1, l2;
        {
            const float4 c0 = __ldg(C4 + gi0), c1 = __ldg(C4 + gi1), c2 = __ldg(C4 + gi2);
            l0.x = c0.x*c0.x; l0.y = c0.y*c0.y; l0.z = c0.z*c0.z; l0.w = c0.w*c0.w;
            l1.x = c1.x*c1.x; l1.y = c1.y*c1.y; l1.z = c1.z*c1.z; l1.w = c1.w*c1.w;
            l2.x = c2.x*c2.x; l2.y = c2.y*c2.y; l2.z = c2.z*c2.z; l2.w = c2.w*c2.w;
        }

        // ---- now prefetch element i+1's eps into L2 (zero registers) ----
        if (i + 1 < BPB && (r16 & 7) == 0) {
            const int nbase = (b + 1) * K1V * 16 + r16;
            pfL2(E4 + nbase + k0 * 16);
            pfL2(E4 + nbase + k0 * 16 + dstride);
            pfL2(E4 + nbase + k0 * 16 + 2 * dstride);
            pfL2(E4 + nbase + k1 * 16);
            pfL2(E4 + nbase + k1 * 16 + dstride);
            pfL2(E4 + nbase + k1 * 16 + 2 * dstride);
        }

        float s0, s1;
        {
            float ax = fmaf(eA0.x, l0.x, m0.x) * fmaf(eB0.x, l1.x, m1.x) * fmaf(eC0.x, l2.x, m2.x);
            float ay = fmaf(eA0.y, l0.y, m0.y) * fmaf(eB0.y, l1.y, m1.y) * fmaf(eC0.y, l2.y, m2.y);
            float az = fmaf(eA0.z, l0.z, m0.z) * fmaf(eB0.z, l1.z, m1.z) * fmaf(eC0.z, l2.z, m2.z);
            float aw = fmaf(eA0.w, l0.w, m0.w) * fmaf(eB0.w, l1.w, m1.w) * fmaf(eC0.w, l2.w, m2.w);
            s0 = (ax + ay) + (az + aw);
        }
        {
            float ax = fmaf(eA1.x, l0.x, m0.x) * fmaf(eB1.x, l1.x, m1.x) * fmaf(eC1.x, l2.x, m2.x);
            float ay = fmaf(eA1.y, l0.y, m0.y) * fmaf(eB1.y, l1.y, m1.y) * fmaf(eC1.y, l2.y, m2.y);
            float az = fmaf(eA1.z, l0.z, m0.z) * fmaf(eB1.z, l1.z, m1.z) * fmaf(eC1.z, l2.z, m2.z);
            float aw = fmaf(eA1.w, l0.w, m0.w) * fmaf(eB1.w, l1.w, m1.w) * fmaf(eC1.w, l2.w, m2.w);
            s1 = (ax + ay) + (az + aw);
        }
        // Reduce over rank within each 16-lane group; both chains run with ILP.
        #pragma unroll
        for (int o = 1; o < 16; o <<= 1) {
            s0 += __shfl_xor_sync(0xffffffffu, s0, o);
            s1 += __shfl_xor_sync(0xffffffffu, s1, o);
        }
        if (r16 == 0) {
            float d0 = s0 - y, d1 = s1 - y;
            lp_acc = fmaf(-0.5f * d0, d0, fmaf(-0.5f * d1, d1, lp_acc));
        }

        // KL on warp 0 only; both 16-lane halves duplicate -> 0.5x at the end.
        // kl = 0.5*(l^2 + m^2 - 1) - ln(l),  l = c^2  (log(S^2) = 2*ln(c^2))
        if (w == 0) {
            float klp;
            klp = 0.5f * ( fmaf(l0.x, l0.x, m0.x*m0.x) + fmaf(l0.y, l0.y, m0.y*m0.y)
                         + fmaf(l0.z, l0.z, m0.z*m0.z) + fmaf(l0.w, l0.w, m0.w*m0.w)
                         + fmaf(l1.x, l1.x, m1.x*m1.x) + fmaf(l1.y, l1.y, m1.y*m1.y)
                         + fmaf(l1.z, l1.z, m1.z*m1.z) + fmaf(l1.w, l1.w, m1.w*m1.w)
                         + fmaf(l2.x, l2.x, m2.x*m2.x) + fmaf(l2.y, l2.y, m2.y*m2.y)
                         + fmaf(l2.z, l2.z, m2.z*m2.z) + fmaf(l2.w, l2.w, m2.w*m2.w));
            klp -= ( fast_ln(l0.x) + fast_ln(l0.y) + fast_ln(l0.z) + fast_ln(l0.w)
                   + fast_ln(l1.x) + fast_ln(l1.y) + fast_ln(l1.z) + fast_ln(l1.w)
                   + fast_ln(l2.x) + fast_ln(l2.y) + fast_ln(l2.z) + fast_ln(l2.w) );
            kl_acc += klp;
        }
    }

    // ---- once-per-block reduction ----
    #pragma unroll
    for (int o = 16; o; o >>= 1) {
        lp_acc += __shfl_xor_sync(0xffffffffu, lp_acc, o);
        kl_acc += __shfl_xor_sync(0xffffffffu, kl_acc, o);
    }
    __shared__ float wlp[8];
    __shared__ float wkl;
    __shared__ bool  isLast;
    if (lane == 0) { wlp[w] = lp_acc; if (w == 0) wkl = 0.5f * kl_acc; }
    __syncthreads();

    if (t == 0) {
        float s = ((wlp[0] + wlp[1]) + (wlp[2] + wlp[3]))
                + ((wlp[4] + wlp[5]) + (wlp[6] + wlp[7]));
        g_part[blockIdx.x] = make_float2(s, wkl);
        __threadfence();
        unsigned int old = atomicAdd(&g_ticket, 1u);
        isLast = (old == (unsigned int)(gridDim.x - 1));
        if (isLast) g_ticket = 0;                    // reset for next replay
    }
    __syncthreads();

    // Last block: final reduction over all per-block partials.
    if (isLast) {
        double se = 0.0, sk = 0.0;
        for (int i = t; i < NBLK; i += 256) {
            float2 p = g_part[i];
            se += (double)p.x;
            sk += (double)p.y;
        }
        #pragma unroll
        for (int o = 16; o; o >>= 1) {
            se += __shfl_xor_sync(0xffffffffu, se, o);
            sk += __shfl_xor_sync(0xffffffffu, sk, o);
        }
        __shared__ double dse[8], dsk[8];
        if (lane == 0) { dse[w] = se; dsk[w] = sk; }
        __syncthreads();
        if (t == 0) {
            double E  = 0.0, KL = 0.0;
            #pragma unroll
            for (int i = 0; i < 8; i++) { E += dse[i]; KL += dsk[i]; }
            E = E / (double)K1V - (double)BATCHV * 0.91893853320467274;
            KL -= 0.5 * (double)NGATH;
            out[0] = (float)(-(100.0 * E - KL / (double)BATCHV));
        }
    }
}

extern "C" void kernel_launch(void* const* d_in, const int* in_sizes, int n_in,
                              void* d_out, int out_size) {
    const int*   entries = (const int*)  d_in[0];
    const float* ys      = (const float*)d_in[1];
    const float* means   = (const float*)d_in[2];
    const float* chols   = (const float*)d_in[3];
    const float* eps     = (const float*)d_in[4];

    fused_k<<<NBLK, 256>>>(entries, ys, means, chols, eps, (float*)d_out);
}